// round 12
// baseline (speedup 1.0000x reference)
#include <cuda_runtime.h>
#include <cuda_bf16.h>
#include <cstdint>

#define HID   128
#define G4    512          // 4*H
#define DIN   2048
#define NBAT  64
#define TSEQ  256
#define MTOT  (NBAT*TSEQ)  // 16384

// ---------------- scratch (device globals: no allocation allowed) ------------
__device__ float g_xp0[(size_t)MTOT * G4];   // layer0 input projection
__device__ float g_seq0[(size_t)MTOT * HID]; // layer0 hidden sequence
__device__ float g_xp1[(size_t)MTOT * G4];   // layer1 input projection

// ============================================================================
// GEMM: C[M,512] = A[M,K] @ W[512,K]^T + (b1 + b2), tf32 tensor cores.
// R11 retile: BM=128, BN=256, BK=32, 512 threads (16 warps, 2x8), 3-stage
// cp.async. Warp tile stays 64x32 (fragment maps identical to the proven R3
// kernel); A re-reads drop 4x -> 2x and the 2 n-blocks share A via L2.
// ============================================================================
#define BM 128
#define BN 256
#define BK 32
#define ASTRIDE 36   // padded fp32 row stride -> conflict-free fragment LDS
#define GSTAGES 3

__device__ __forceinline__ void cp16(void* s, const void* g) {
    uint32_t sa = (uint32_t)__cvta_generic_to_shared(s);
    asm volatile("cp.async.cg.shared.global [%0], [%1], 16;" :: "r"(sa), "l"(g));
}
__device__ __forceinline__ uint32_t f2tf32(float f) {
    uint32_t u;
    asm("cvt.rna.tf32.f32 %0, %1;" : "=r"(u) : "f"(f));
    return u;
}
__device__ __forceinline__ void mma_tf32(float* c, const uint32_t* a, const uint32_t* b) {
    asm volatile(
        "mma.sync.aligned.m16n8k8.row.col.f32.tf32.tf32.f32 "
        "{%0,%1,%2,%3}, {%4,%5,%6,%7}, {%8,%9}, {%0,%1,%2,%3};"
        : "+f"(c[0]), "+f"(c[1]), "+f"(c[2]), "+f"(c[3])
        : "r"(a[0]), "r"(a[1]), "r"(a[2]), "r"(a[3]), "r"(b[0]), "r"(b[1]));
}

// 3 stages x (A 128 + B 256 rows) x ASTRIDE floats
#define GEMM_SMEM (GSTAGES * (BM + BN) * ASTRIDE * 4)   // 165888 B

__global__ void __launch_bounds__(512, 1)
gemm_bias(const float* __restrict__ A, const float* __restrict__ W,
          const float* __restrict__ b1, const float* __restrict__ b2,
          float* __restrict__ C, int K)
{
    extern __shared__ float sm[];
    float* As = sm;                                   // [GSTAGES][BM][ASTRIDE]
    float* Bs = sm + GSTAGES * BM * ASTRIDE;          // [GSTAGES][BN][ASTRIDE]

    const int tid  = threadIdx.x;
    const int m0   = blockIdx.y * BM;
    const int n0   = blockIdx.x * BN;
    const int warp = tid >> 5, lane = tid & 31;
    const int wm   = warp >> 3, wn = warp & 7;        // warp grid 2x8, tile 64x32
    const int gid  = lane >> 2, tig = lane & 3;

    float acc[4][4][4];
#pragma unroll
    for (int i = 0; i < 4; i++)
#pragma unroll
        for (int jx = 0; jx < 4; jx++)
#pragma unroll
            for (int r = 0; r < 4; r++) acc[i][jx][r] = 0.f;

    const int row_l = tid >> 3;        // 0..63
    const int c4    = (tid & 7) * 4;   // float offset 0..28
    const int NK    = K / BK;

    auto LOAD = [&](int kc, int buf) {
        const size_t k0 = (size_t)kc * BK;
        const float* Ag = A + (size_t)(m0 + row_l) * K + k0 + c4;
        const float* Wg = W + (size_t)(n0 + row_l) * K + k0 + c4;
        float* Ad = As + buf * BM * ASTRIDE + row_l * ASTRIDE + c4;
        float* Bd = Bs + buf * BN * ASTRIDE + row_l * ASTRIDE + c4;
#pragma unroll
        for (int i = 0; i < 2; i++)    // A: 2 x 64 rows = 128
            cp16(Ad + i * 64 * ASTRIDE, Ag + (size_t)(i * 64) * K);
#pragma unroll
        for (int i = 0; i < 4; i++)    // B: 4 x 64 rows = 256
            cp16(Bd + i * 64 * ASTRIDE, Wg + (size_t)(i * 64) * K);
        asm volatile("cp.async.commit_group;");
    };

    // prologue: 2 stages in flight
    LOAD(0, 0);
    LOAD(1, 1);

    for (int kc = 0; kc < NK; kc++) {
        const int cur = kc % GSTAGES;
        if (kc + 2 < NK) {
            LOAD(kc + 2, (kc + 2) % GSTAGES);
            asm volatile("cp.async.wait_group 2;");
        } else if (kc + 1 < NK) {
            asm volatile("cp.async.wait_group 1;");
        } else {
            asm volatile("cp.async.wait_group 0;");
        }
        __syncthreads();

        const float* Ab = As + cur * BM * ASTRIDE;
        const float* Bb = Bs + cur * BN * ASTRIDE;
#pragma unroll
        for (int kk = 0; kk < 4; kk++) {
            uint32_t af[4][4], bf[4][2];
#pragma unroll
            for (int ti = 0; ti < 4; ti++) {
                const float* ap = Ab + (wm * 64 + ti * 16 + gid) * ASTRIDE + kk * 8 + tig;
                af[ti][0] = f2tf32(ap[0]);
                af[ti][1] = f2tf32(ap[8 * ASTRIDE]);
                af[ti][2] = f2tf32(ap[4]);
                af[ti][3] = f2tf32(ap[8 * ASTRIDE + 4]);
            }
#pragma unroll
            for (int tj = 0; tj < 4; tj++) {
                const float* bp = Bb + (wn * 32 + tj * 8 + gid) * ASTRIDE + kk * 8 + tig;
                bf[tj][0] = f2tf32(bp[0]);
                bf[tj][1] = f2tf32(bp[4]);
            }
#pragma unroll
            for (int ti = 0; ti < 4; ti++)
#pragma unroll
                for (int tj = 0; tj < 4; tj++)
                    mma_tf32(acc[ti][tj], af[ti], bf[tj]);
        }
        __syncthreads();
    }

    // epilogue: add both biases, write fp32
#pragma unroll
    for (int ti = 0; ti < 4; ti++) {
        const int r0 = m0 + wm * 64 + ti * 16 + gid;
#pragma unroll
        for (int tj = 0; tj < 4; tj++) {
            const int col = n0 + wn * 32 + tj * 8 + tig * 2;
            const float bx = b1[col] + b2[col];
            const float by = b1[col + 1] + b2[col + 1];
            float2 v0 = { acc[ti][tj][0] + bx, acc[ti][tj][1] + by };
            float2 v1 = { acc[ti][tj][2] + bx, acc[ti][tj][3] + by };
            *(float2*)(C + (size_t)r0 * G4 + col)       = v0;
            *(float2*)(C + (size_t)(r0 + 8) * G4 + col) = v1;
        }
    }
}

// ============================================================================
// LSTM recurrence (UNCHANGED from R11 winner — 256us/layer measured).
// 1 CTA per batch element, 512 threads. Whh[j][0:96] in registers as 48
// packed f32x2, Whh[j][96:128] in smem transposed. fma.rn.f32x2 matvec.
// ============================================================================
#define REC_SMEM (8 * 512 * 16 + (HID + G4) * 4)   // 68096 B

__device__ __forceinline__ float fast_sigmoid(float x) {
    float e = __expf(-fabsf(x));
    float r = __fdividef(1.f, 1.f + e);
    return x >= 0.f ? r : 1.f - r;
}
__device__ __forceinline__ float fast_tanh(float x) {
    float e = __expf(-2.f * fabsf(x));
    float r = __fdividef(1.f - e, 1.f + e);
    return x >= 0.f ? r : -r;
}
__device__ __forceinline__ uint64_t ffma2(uint64_t a, uint64_t b, uint64_t c) {
    uint64_t d;
    asm("fma.rn.f32x2 %0, %1, %2, %3;" : "=l"(d) : "l"(a), "l"(b), "l"(c));
    return d;
}
__device__ __forceinline__ float2 unpack2(uint64_t v) {
    float2 f;
    asm("mov.b64 {%0, %1}, %2;" : "=f"(f.x), "=f"(f.y) : "l"(v));
    return f;
}

__global__ void __launch_bounds__(512, 1)
lstm_layer(const float* __restrict__ xp, const float* __restrict__ Whh,
           float* __restrict__ seq_out,
           const float* __restrict__ Wfc, const float* __restrict__ bfc,
           float* __restrict__ out)
{
    extern __shared__ __align__(16) char smraw[];
    ulonglong2* Wsh2 = (ulonglong2*)smraw;                 // [8][512]
    float* h_sh = (float*)(smraw + 8 * 512 * 16);          // 128 floats
    float* gbuf = h_sh + HID;                              // 512 floats

    const int j = threadIdx.x;
    const int b = blockIdx.x;

    // ---- weights: cols 0..95 -> 48 packed f32x2 regs; cols 96..127 -> smem ----
    const ulonglong2* wrow = (const ulonglong2*)(Whh + (size_t)j * HID);
    uint64_t W2[48];
#pragma unroll
    for (int k = 0; k < 24; k++) {          // 24 x 16B = 96 floats
        ulonglong2 v = wrow[k];
        W2[2 * k]     = v.x;
        W2[2 * k + 1] = v.y;
    }
#pragma unroll
    for (int k = 0; k < 8; k++)             // cols 96..127, transposed
        Wsh2[k * 512 + j] = wrow[24 + k];

    if (j < HID) h_sh[j] = 0.f;
    __syncthreads();

    const float* xrow = xp + (size_t)b * TSEQ * G4 + j;
    const int gate = j >> 7;                // 0=i 1=f 2=g 3=o
    float c = 0.f, h = 0.f;
    float xv = __ldg(xrow);                 // prefetch t=0

    const ulonglong2* h2 = (const ulonglong2*)h_sh;   // 32 x 16B = 128 floats

    for (int t = 0; t < TSEQ; t++) {
        float xn = (t + 1 < TSEQ) ? __ldg(xrow + (size_t)(t + 1) * G4) : 0.f;

        // matvec: 64 FFMA2 (128 MACs), two accumulator chains for ILP
        uint64_t a0 = 0ull, a1 = 0ull;
#pragma unroll
        for (int k = 0; k < 24; k++) {                 // h[0..95] x reg weights
            ulonglong2 hv = h2[k];
            a0 = ffma2(W2[2 * k],     hv.x, a0);
            a1 = ffma2(W2[2 * k + 1], hv.y, a1);
        }
#pragma unroll
        for (int k = 0; k < 8; k++) {                  // h[96..127] x smem weights
            ulonglong2 wv = Wsh2[k * 512 + j];
            ulonglong2 hv = h2[24 + k];
            a0 = ffma2(wv.x, hv.x, a0);
            a1 = ffma2(wv.y, hv.y, a1);
        }
        float2 f0 = unpack2(a0), f1 = unpack2(a1);
        float g = ((f0.x + f0.y) + (f1.x + f1.y)) + xv;

        // activation spread across all 512 threads
        gbuf[j] = (gate == 2) ? fast_tanh(g) : fast_sigmoid(g);
        __syncthreads();

        if (j < HID) {
            float gi = gbuf[j];
            float gf = gbuf[j + 128];
            float gg = gbuf[j + 256];
            float go = gbuf[j + 384];
            c = gf * c + gi * gg;
            h = go * fast_tanh(c);
            h_sh[j] = h;
            if (seq_out) seq_out[((size_t)b * TSEQ + t) * HID + j] = h;
        }
        __syncthreads();
        xv = xn;
    }

    // ---- fused FC head (layer 1 only): out[b] = h_T . Wfc + bfc ----
    if (out) {
        if (j < HID) gbuf[j] = h * __ldg(Wfc + j);
        __syncthreads();
        if (j == 0) {
            float s = 0.f;
#pragma unroll
            for (int n = 0; n < HID; n++) s += gbuf[n];
            out[b] = s + __ldg(bfc);
        }
    }
}

// ============================================================================
// launcher
// ============================================================================
extern "C" void kernel_launch(void* const* d_in, const int* in_sizes, int n_in,
                              void* d_out, int out_size)
{
    const float* x    = (const float*)d_in[0];
    const float* Wih0 = (const float*)d_in[1];
    const float* Whh0 = (const float*)d_in[2];
    const float* bih0 = (const float*)d_in[3];
    const float* bhh0 = (const float*)d_in[4];
    const float* Wih1 = (const float*)d_in[5];
    const float* Whh1 = (const float*)d_in[6];
    const float* bih1 = (const float*)d_in[7];
    const float* bhh1 = (const float*)d_in[8];
    const float* Wfc  = (const float*)d_in[9];
    const float* bfc  = (const float*)d_in[10];
    float* out = (float*)d_out;

    float *xp0, *seq0, *xp1;
    cudaGetSymbolAddress((void**)&xp0,  g_xp0);
    cudaGetSymbolAddress((void**)&seq0, g_seq0);
    cudaGetSymbolAddress((void**)&xp1,  g_xp1);

    cudaFuncSetAttribute(gemm_bias,
                         cudaFuncAttributeMaxDynamicSharedMemorySize, GEMM_SMEM);
    cudaFuncSetAttribute(lstm_layer,
                         cudaFuncAttributeMaxDynamicSharedMemorySize, REC_SMEM);

    dim3 ggrid(G4 / BN, MTOT / BM);   // (2, 128) = 256 CTAs

    // layer 0 input projection: [16384,2048] @ [512,2048]^T
    gemm_bias<<<ggrid, 512, GEMM_SMEM>>>(x, Wih0, bih0, bhh0, xp0, DIN);
    // layer 0 recurrence -> seq0
    lstm_layer<<<NBAT, 512, REC_SMEM>>>(xp0, Whh0, seq0, nullptr, nullptr, nullptr);
    // layer 1 input projection: [16384,128] @ [512,128]^T
    gemm_bias<<<ggrid, 512, GEMM_SMEM>>>(seq0, Wih1, bih1, bhh1, xp1, HID);
    // layer 1 recurrence + fused FC head
    lstm_layer<<<NBAT, 512, REC_SMEM>>>(xp1, Whh1, nullptr, Wfc, bfc, out);
}

// round 13
// speedup vs baseline: 1.1240x; 1.1240x over previous
#include <cuda_runtime.h>
#include <cuda_bf16.h>
#include <cuda_fp16.h>
#include <cstdint>

#define HID   128
#define G4    512          // 4*H
#define DIN   2048
#define NBAT  64
#define TSEQ  256
#define MTOT  (NBAT*TSEQ)  // 16384

// ---------------- scratch (device globals: no allocation allowed) ------------
__device__ float g_xp0[(size_t)MTOT * G4];   // layer0 input projection
__device__ float g_seq0[(size_t)MTOT * HID]; // layer0 hidden sequence
__device__ float g_xp1[(size_t)MTOT * G4];   // layer1 input projection

// ============================================================================
// GEMM: C[M,512] = A[M,K] @ W[512,K]^T + (b1 + b2), tf32 tensor cores.
// REVERTED verbatim to the R3 config (256 thr, BM=BN=128, 2-stage) — the
// version measured inside the 786.8us best run. R12's BN=256 retile regressed.
// ============================================================================
#define BM 128
#define BN 128
#define BK 32
#define ASTRIDE 36   // padded fp32 row stride -> conflict-free fragment LDS

__device__ __forceinline__ void cp16(void* s, const void* g) {
    uint32_t sa = (uint32_t)__cvta_generic_to_shared(s);
    asm volatile("cp.async.cg.shared.global [%0], [%1], 16;" :: "r"(sa), "l"(g));
}
__device__ __forceinline__ uint32_t f2tf32(float f) {
    uint32_t u;
    asm("cvt.rna.tf32.f32 %0, %1;" : "=r"(u) : "f"(f));
    return u;
}
__device__ __forceinline__ void mma_tf32(float* c, const uint32_t* a, const uint32_t* b) {
    asm volatile(
        "mma.sync.aligned.m16n8k8.row.col.f32.tf32.tf32.f32 "
        "{%0,%1,%2,%3}, {%4,%5,%6,%7}, {%8,%9}, {%0,%1,%2,%3};"
        : "+f"(c[0]), "+f"(c[1]), "+f"(c[2]), "+f"(c[3])
        : "r"(a[0]), "r"(a[1]), "r"(a[2]), "r"(a[3]), "r"(b[0]), "r"(b[1]));
}

#define GEMM_SMEM (4 * BM * ASTRIDE * 4)   // 2 bufs A + 2 bufs B, fp32 = 73728 B

__global__ void __launch_bounds__(256, 2)
gemm_bias(const float* __restrict__ A, const float* __restrict__ W,
          const float* __restrict__ b1, const float* __restrict__ b2,
          float* __restrict__ C, int K)
{
    extern __shared__ float sm[];
    float* As = sm;                       // [2][BM][ASTRIDE]
    float* Bs = sm + 2 * BM * ASTRIDE;    // [2][BN][ASTRIDE]

    const int tid  = threadIdx.x;
    const int m0   = blockIdx.y * BM;
    const int n0   = blockIdx.x * BN;
    const int warp = tid >> 5, lane = tid & 31;
    const int wm   = warp >> 2, wn = warp & 3;      // warp grid 2x4, tile 64x32
    const int gid  = lane >> 2, tig = lane & 3;

    float acc[4][4][4];
#pragma unroll
    for (int i = 0; i < 4; i++)
#pragma unroll
        for (int jx = 0; jx < 4; jx++)
#pragma unroll
            for (int r = 0; r < 4; r++) acc[i][jx][r] = 0.f;

    const int row_l = tid >> 3;        // 0..31
    const int c4    = (tid & 7) * 4;   // float offset 0..28
    const int NK    = K / BK;

    auto LOAD = [&](int kc, int buf) {
        const size_t k0 = (size_t)kc * BK;
        const float* Ag = A + (size_t)(m0 + row_l) * K + k0 + c4;
        const float* Wg = W + (size_t)(n0 + row_l) * K + k0 + c4;
        float* Ad = As + buf * BM * ASTRIDE + row_l * ASTRIDE + c4;
        float* Bd = Bs + buf * BM * ASTRIDE + row_l * ASTRIDE + c4;
#pragma unroll
        for (int i = 0; i < 4; i++) {
            cp16(Ad + i * 32 * ASTRIDE, Ag + (size_t)(i * 32) * K);
            cp16(Bd + i * 32 * ASTRIDE, Wg + (size_t)(i * 32) * K);
        }
        asm volatile("cp.async.commit_group;");
    };

    LOAD(0, 0);
    for (int kc = 0; kc < NK; kc++) {
        const int cur = kc & 1;
        if (kc + 1 < NK) {
            LOAD(kc + 1, cur ^ 1);
            asm volatile("cp.async.wait_group 1;");
        } else {
            asm volatile("cp.async.wait_group 0;");
        }
        __syncthreads();

        const float* Ab = As + cur * BM * ASTRIDE;
        const float* Bb = Bs + cur * BM * ASTRIDE;
#pragma unroll
        for (int kk = 0; kk < 4; kk++) {
            uint32_t af[4][4], bf[4][2];
#pragma unroll
            for (int ti = 0; ti < 4; ti++) {
                const float* ap = Ab + (wm * 64 + ti * 16 + gid) * ASTRIDE + kk * 8 + tig;
                af[ti][0] = f2tf32(ap[0]);
                af[ti][1] = f2tf32(ap[8 * ASTRIDE]);
                af[ti][2] = f2tf32(ap[4]);
                af[ti][3] = f2tf32(ap[8 * ASTRIDE + 4]);
            }
#pragma unroll
            for (int tj = 0; tj < 4; tj++) {
                const float* bp = Bb + (wn * 32 + tj * 8 + gid) * ASTRIDE + kk * 8 + tig;
                bf[tj][0] = f2tf32(bp[0]);
                bf[tj][1] = f2tf32(bp[4]);
            }
#pragma unroll
            for (int ti = 0; ti < 4; ti++)
#pragma unroll
                for (int tj = 0; tj < 4; tj++)
                    mma_tf32(acc[ti][tj], af[ti], bf[tj]);
        }
        __syncthreads();
    }

#pragma unroll
    for (int ti = 0; ti < 4; ti++) {
        const int r0 = m0 + wm * 64 + ti * 16 + gid;
#pragma unroll
        for (int tj = 0; tj < 4; tj++) {
            const int col = n0 + wn * 32 + tj * 8 + tig * 2;
            const float bx = b1[col] + b2[col];
            const float by = b1[col + 1] + b2[col + 1];
            float2 v0 = { acc[ti][tj][0] + bx, acc[ti][tj][1] + by };
            float2 v1 = { acc[ti][tj][2] + bx, acc[ti][tj][3] + by };
            *(float2*)(C + (size_t)r0 * G4 + col)       = v0;
            *(float2*)(C + (size_t)(r0 + 8) * G4 + col) = v1;
        }
    }
}

// ============================================================================
// LSTM recurrence: 1 CTA per batch element, 512 threads.
// Whh[j][0:96] in registers as 48 packed f32x2 (96 regs).
// Whh[j][96:128] in smem as fp16 half2, transposed [8][512] uint2 —
// LDS.64 spread = 2 wf/access (vs 4 for fp32 LDS.128): tail traffic halved.
// Converted to fp32 in-register; all accumulation stays fp32 via fma.rn.f32x2.
// ============================================================================
// dynamic smem: Wsh[8][512] uint2 (32KB) + h_sh[128] + gbuf[512]
#define REC_SMEM (8 * 512 * 8 + (HID + G4) * 4)   // 35328 B

__device__ __forceinline__ float fast_sigmoid(float x) {
    float e = __expf(-fabsf(x));
    float r = __fdividef(1.f, 1.f + e);
    return x >= 0.f ? r : 1.f - r;
}
__device__ __forceinline__ float fast_tanh(float x) {
    float e = __expf(-2.f * fabsf(x));
    float r = __fdividef(1.f - e, 1.f + e);
    return x >= 0.f ? r : -r;
}
__device__ __forceinline__ uint64_t ffma2(uint64_t a, uint64_t b, uint64_t c) {
    uint64_t d;
    asm("fma.rn.f32x2 %0, %1, %2, %3;" : "=l"(d) : "l"(a), "l"(b), "l"(c));
    return d;
}
__device__ __forceinline__ float2 unpack2(uint64_t v) {
    float2 f;
    asm("mov.b64 {%0, %1}, %2;" : "=f"(f.x), "=f"(f.y) : "l"(v));
    return f;
}
__device__ __forceinline__ uint64_t pack2(float lo, float hi) {
    uint64_t r;
    asm("mov.b64 %0, {%1, %2};" : "=l"(r) : "f"(lo), "f"(hi));
    return r;
}

__global__ void __launch_bounds__(512, 1)
lstm_layer(const float* __restrict__ xp, const float* __restrict__ Whh,
           float* __restrict__ seq_out,
           const float* __restrict__ Wfc, const float* __restrict__ bfc,
           float* __restrict__ out)
{
    extern __shared__ __align__(16) char smraw[];
    uint2* Wsh = (uint2*)smraw;                            // [8][512] half2 pairs
    float* h_sh = (float*)(smraw + 8 * 512 * 8);           // 128 floats
    float* gbuf = h_sh + HID;                              // 512 floats

    const int j = threadIdx.x;
    const int b = blockIdx.x;

    // ---- weights: cols 0..95 -> 48 packed f32x2 regs; cols 96..127 -> fp16 smem
    const ulonglong2* wrow = (const ulonglong2*)(Whh + (size_t)j * HID);
    uint64_t W2[48];
#pragma unroll
    for (int k = 0; k < 24; k++) {          // 24 x 16B = 96 floats
        ulonglong2 v = wrow[k];
        W2[2 * k]     = v.x;
        W2[2 * k + 1] = v.y;
    }
    {
        const float4* wtail = (const float4*)(Whh + (size_t)j * HID + 96);
#pragma unroll
        for (int k = 0; k < 8; k++) {       // cols 96+4k .. 99+4k
            float4 v = wtail[k];
            __half2 h0 = __floats2half2_rn(v.x, v.y);
            __half2 h1 = __floats2half2_rn(v.z, v.w);
            uint2 pk;
            pk.x = *(uint32_t*)&h0;
            pk.y = *(uint32_t*)&h1;
            Wsh[k * 512 + j] = pk;
        }
    }

    if (j < HID) h_sh[j] = 0.f;
    __syncthreads();

    const float* xrow = xp + (size_t)b * TSEQ * G4 + j;
    const int gate = j >> 7;                // 0=i 1=f 2=g 3=o
    float c = 0.f, h = 0.f;
    float xv = __ldg(xrow);                 // prefetch t=0

    const ulonglong2* h2 = (const ulonglong2*)h_sh;   // 32 x 16B = 128 floats

    for (int t = 0; t < TSEQ; t++) {
        float xn = (t + 1 < TSEQ) ? __ldg(xrow + (size_t)(t + 1) * G4) : 0.f;

        // matvec: 64 FFMA2 (128 MACs), two accumulator chains for ILP
        uint64_t a0 = 0ull, a1 = 0ull;
#pragma unroll
        for (int k = 0; k < 24; k++) {                 // h[0..95] x fp32 reg weights
            ulonglong2 hv = h2[k];
            a0 = ffma2(W2[2 * k],     hv.x, a0);
            a1 = ffma2(W2[2 * k + 1], hv.y, a1);
        }
#pragma unroll
        for (int k = 0; k < 8; k++) {                  // h[96..127] x fp16 smem weights
            uint2 wv = Wsh[k * 512 + j];
            float2 w0 = __half22float2(*(__half2*)&wv.x);
            float2 w1 = __half22float2(*(__half2*)&wv.y);
            ulonglong2 hv = h2[24 + k];
            a0 = ffma2(pack2(w0.x, w0.y), hv.x, a0);
            a1 = ffma2(pack2(w1.x, w1.y), hv.y, a1);
        }
        float2 f0 = unpack2(a0), f1 = unpack2(a1);
        float g = ((f0.x + f0.y) + (f1.x + f1.y)) + xv;

        // activation spread across all 512 threads
        gbuf[j] = (gate == 2) ? fast_tanh(g) : fast_sigmoid(g);
        __syncthreads();

        if (j < HID) {
            float gi = gbuf[j];
            float gf = gbuf[j + 128];
            float gg = gbuf[j + 256];
            float go = gbuf[j + 384];
            c = gf * c + gi * gg;
            h = go * fast_tanh(c);
            h_sh[j] = h;
            if (seq_out) seq_out[((size_t)b * TSEQ + t) * HID + j] = h;
        }
        __syncthreads();
        xv = xn;
    }

    // ---- fused FC head (layer 1 only): out[b] = h_T . Wfc + bfc ----
    if (out) {
        if (j < HID) gbuf[j] = h * __ldg(Wfc + j);
        __syncthreads();
        if (j == 0) {
            float s = 0.f;
#pragma unroll
            for (int n = 0; n < HID; n++) s += gbuf[n];
            out[b] = s + __ldg(bfc);
        }
    }
}

// ============================================================================
// launcher
// ============================================================================
extern "C" void kernel_launch(void* const* d_in, const int* in_sizes, int n_in,
                              void* d_out, int out_size)
{
    const float* x    = (const float*)d_in[0];
    const float* Wih0 = (const float*)d_in[1];
    const float* Whh0 = (const float*)d_in[2];
    const float* bih0 = (const float*)d_in[3];
    const float* bhh0 = (const float*)d_in[4];
    const float* Wih1 = (const float*)d_in[5];
    const float* Whh1 = (const float*)d_in[6];
    const float* bih1 = (const float*)d_in[7];
    const float* bhh1 = (const float*)d_in[8];
    const float* Wfc  = (const float*)d_in[9];
    const float* bfc  = (const float*)d_in[10];
    float* out = (float*)d_out;

    float *xp0, *seq0, *xp1;
    cudaGetSymbolAddress((void**)&xp0,  g_xp0);
    cudaGetSymbolAddress((void**)&seq0, g_seq0);
    cudaGetSymbolAddress((void**)&xp1,  g_xp1);

    cudaFuncSetAttribute(gemm_bias,
                         cudaFuncAttributeMaxDynamicSharedMemorySize, GEMM_SMEM);
    cudaFuncSetAttribute(lstm_layer,
                         cudaFuncAttributeMaxDynamicSharedMemorySize, REC_SMEM);

    dim3 ggrid(G4 / BN, MTOT / BM);   // (4, 128) = 512 CTAs

    // layer 0 input projection: [16384,2048] @ [512,2048]^T
    gemm_bias<<<ggrid, 256, GEMM_SMEM>>>(x, Wih0, bih0, bhh0, xp0, DIN);
    // layer 0 recurrence -> seq0
    lstm_layer<<<NBAT, 512, REC_SMEM>>>(xp0, Whh0, seq0, nullptr, nullptr, nullptr);
    // layer 1 input projection: [16384,128] @ [512,128]^T
    gemm_bias<<<ggrid, 256, GEMM_SMEM>>>(seq0, Wih1, bih1, bhh1, xp1, HID);
    // layer 1 recurrence + fused FC head
    lstm_layer<<<NBAT, 512, REC_SMEM>>>(xp1, Whh1, nullptr, Wfc, bfc, out);
}